// round 16
// baseline (speedup 1.0000x reference)
#include <cuda_runtime.h>
#include <cuda_fp16.h>
#include <cstdint>

#define B_ 2
#define S_ 2048
#define D_ 4096
#define NQKV 12288
#define MROWS 4096

// ---------------- scratch (fp16 operands) ------------------------------------
__device__ __half g_WqkvT[(size_t)NQKV * D_];
__device__ __half g_qkv  [(size_t)MROWS * NQKV];
__device__ __half g_WoutT[(size_t)D_ * D_];
__device__ __half g_ctx  [(size_t)MROWS * D_];
__device__ __half g_hs16 [(size_t)MROWS * D_];

__device__ __forceinline__ uint32_t smem_u32(const void* p) {
    uint32_t a;
    asm("{ .reg .u64 t; cvta.to.shared.u64 t, %1; cvt.u32.u64 %0, t; }" : "=r"(a) : "l"(p));
    return a;
}
__device__ __forceinline__ void ldsm4(uint32_t& r0, uint32_t& r1, uint32_t& r2,
                                      uint32_t& r3, uint32_t addr) {
    asm volatile("ldmatrix.sync.aligned.m8n8.x4.shared.b16 {%0,%1,%2,%3}, [%4];"
                 : "=r"(r0), "=r"(r1), "=r"(r2), "=r"(r3) : "r"(addr));
}
__device__ __forceinline__ void ldsm4t(uint32_t& r0, uint32_t& r1, uint32_t& r2,
                                       uint32_t& r3, uint32_t addr) {
    asm volatile("ldmatrix.sync.aligned.m8n8.x4.trans.shared.b16 {%0,%1,%2,%3}, [%4];"
                 : "=r"(r0), "=r"(r1), "=r"(r2), "=r"(r3) : "r"(addr));
}
#define CPA16(dst, src) \
    asm volatile("cp.async.cg.shared.global [%0], [%1], 16;" :: "r"(dst), "l"(src))
#define MMA16(d, a, b0_, b1_) \
    asm volatile("mma.sync.aligned.m16n8k16.row.col.f32.f16.f16.f32 " \
                 "{%0,%1,%2,%3}, {%4,%5,%6,%7}, {%8,%9}, {%0,%1,%2,%3};" \
                 : "+f"(d[0]), "+f"(d[1]), "+f"(d[2]), "+f"(d[3]) \
                 : "r"(a[0]), "r"(a[1]), "r"(a[2]), "r"(a[3]), "r"(b0_), "r"(b1_))

// ---------------- GPTQ dequant v2 (R14, verified) ----------------------------
__global__ __launch_bounds__(256) void dequant_v2(const int* __restrict__ qw,
                                                  const int* __restrict__ qz,
                                                  const float* __restrict__ sc,
                                                  __half* __restrict__ Wt, int N) {
    __shared__ uint4 t[64][17];
    const int tid = threadIdx.x;
    const int ntiles = N >> 6;
    const int n0 = (blockIdx.x % ntiles) << 6;
    const int r0 = (blockIdx.x / ntiles) << 4;
    const int g = r0 >> 4;

#pragma unroll
    for (int i = 0; i < 4; i++) {
        int f = tid + i * 256;
        int nl = f & 63, rl = f >> 6;
        int n = n0 + nl, r = r0 + rl;
        unsigned w = (unsigned)qw[(size_t)r * N + n];
        unsigned z = (unsigned)qz[(size_t)g * (N / 8) + (n >> 3)];
        int zp = (int)((z >> ((n & 7) * 4)) & 15u) + 1;
        float s = sc[(size_t)g * N + n];
        __half2 h[4];
#pragma unroll
        for (int j = 0; j < 4; j++) {
            float v0 = s * (float)((int)((w >> (j * 8)) & 15u) - zp);
            float v1 = s * (float)((int)((w >> (j * 8 + 4)) & 15u) - zp);
            h[j] = __floats2half2_rn(v0, v1);
        }
        t[nl][rl] = *(uint4*)h;
    }
    __syncthreads();
#pragma unroll
    for (int i = 0; i < 4; i++) {
        int f = tid + i * 256;
        int nl = f >> 4, seg = f & 15;
        *(uint4*)(Wt + (size_t)(n0 + nl) * D_ + (size_t)r0 * 8 + seg * 8) = t[nl][seg];
    }
}

__global__ void h16_copy_kernel(const float4* __restrict__ src, uint4* __restrict__ dst) {
    size_t i = (size_t)blockIdx.x * blockDim.x + threadIdx.x;
    float4 a = src[2 * i], b = src[2 * i + 1];
    __half2 h[4] = {__floats2half2_rn(a.x, a.y), __floats2half2_rn(a.z, a.w),
                    __floats2half2_rn(b.x, b.y), __floats2half2_rn(b.z, b.w)};
    dst[i] = *(uint4*)h;
}

// ---------------- fp16 mma GEMM v4 (R11, verified) ---------------------------
#define STG4 32768
__global__ __launch_bounds__(128, 2) void fp16_gemm(const __half* __restrict__ A,
                                                    const __half* __restrict__ Bt,
                                                    void* __restrict__ Cv, int N,
                                                    int out_half) {
    extern __shared__ char smraw[];
    const uint32_t sb = smem_u32(smraw);
    const int tid = threadIdx.x;
    const int L = tid & 31;
    const int wid = tid >> 5;
    const int wm = wid >> 1, wn = wid & 1;

    const int gx = N >> 7;
    int rpg = gx << 4;
    int grp = blockIdx.x / rpg;
    int rem = blockIdx.x - grp * rpg;
    int by = (grp << 4) + (rem & 15);
    int bx = rem >> 4;

    const __half* Ag = A + (size_t)(by * 128) * 4096;
    const __half* Bg = Bt + (size_t)(bx * 128) * 4096;

    auto stage_load = [&](int kc, int st) {
        uint32_t sA = sb + st * STG4;
        uint32_t sB = sA + 16384;
        const __half* Ap = Ag + kc * 64;
        const __half* Bp = Bg + kc * 64;
#pragma unroll
        for (int i = 0; i < 8; i++) {
            int f = tid + i * 128, r = f >> 3, c = f & 7;
            uint32_t off = r * 128 + ((c * 16) ^ ((r & 7) << 4));
            CPA16(sA + off, Ap + (size_t)r * 4096 + c * 8);
            CPA16(sB + off, Bp + (size_t)r * 4096 + c * 8);
        }
        asm volatile("cp.async.commit_group;" ::: "memory");
    };

    float acc[4][8][4];
#pragma unroll
    for (int mt = 0; mt < 4; mt++)
#pragma unroll
        for (int nt = 0; nt < 8; nt++)
#pragma unroll
            for (int j = 0; j < 4; j++) acc[mt][nt][j] = 0.f;

    stage_load(0, 0);
    stage_load(1, 1);

#pragma unroll 1
    for (int i = 0; i < 64; i++) {
        if (i < 63) asm volatile("cp.async.wait_group 1;" ::: "memory");
        else        asm volatile("cp.async.wait_group 0;" ::: "memory");
        __syncthreads();
        if (i + 2 < 64) stage_load(i + 2, (i + 2) % 3);
        uint32_t sA = sb + (i % 3) * STG4;
        uint32_t sB = sA + 16384;
#pragma unroll
        for (int ks = 0; ks < 4; ks++) {
            uint32_t a[4][4];
#pragma unroll
            for (int mt = 0; mt < 4; mt++) {
                int row = wm * 64 + mt * 16 + (L & 15);
                ldsm4(a[mt][0], a[mt][1], a[mt][2], a[mt][3],
                      sA + row * 128 + (((2 * ks + (L >> 4)) * 16) ^ ((row & 7) << 4)));
            }
#pragma unroll
            for (int np = 0; np < 4; np++) {
                int n = wn * 64 + np * 16 + ((L & 7) | ((L & 16) >> 1));
                uint32_t b0, b1, b2, b3;
                ldsm4(b0, b1, b2, b3,
                      sB + n * 128 + (((2 * ks + ((L >> 3) & 1)) * 16) ^ ((n & 7) << 4)));
#pragma unroll
                for (int mt = 0; mt < 4; mt++) {
                    MMA16(acc[mt][2 * np], a[mt], b0, b1);
                    MMA16(acc[mt][2 * np + 1], a[mt], b2, b3);
                }
            }
        }
    }

    const int row0 = by * 128 + wm * 64 + (L >> 2);
    const int col0 = bx * 128 + wn * 64 + 2 * (L & 3);
    if (out_half) {
        __half* C = (__half*)Cv;
#pragma unroll
        for (int mt = 0; mt < 4; mt++)
#pragma unroll
            for (int nt = 0; nt < 8; nt++) {
                __half* p = C + (size_t)(row0 + mt * 16) * N + col0 + nt * 8;
                *(__half2*)p = __floats2half2_rn(acc[mt][nt][0], acc[mt][nt][1]);
                *(__half2*)(p + (size_t)8 * N) = __floats2half2_rn(acc[mt][nt][2], acc[mt][nt][3]);
            }
    } else {
        float* C = (float*)Cv;
#pragma unroll
        for (int mt = 0; mt < 4; mt++)
#pragma unroll
            for (int nt = 0; nt < 8; nt++) {
                float* p = C + (size_t)(row0 + mt * 16) * N + col0 + nt * 8;
                *(float2*)p = make_float2(acc[mt][nt][0], acc[mt][nt][1]);
                *(float2*)(p + (size_t)8 * N) = make_float2(acc[mt][nt][2], acc[mt][nt][3]);
            }
    }
}

// ---------------- RoPE on fp16 qkv --------------------------------------------
__global__ void rope_kernel(__half* __restrict__ qkv) {
    int bs = blockIdx.x;
    int s = bs & (S_ - 1);
    int h = threadIdx.x >> 5;
    int i = threadIdx.x & 31;
    float inv_freq = 1.0f / powf(10000.0f, (float)(2 * i) / 64.0f);
    float ang = (float)s * inv_freq;
    float sn = sinf(ang), cs = cosf(ang);
    size_t base = (size_t)bs * NQKV + (size_t)h * 256 + 2 * i;
    __half2* q = (__half2*)(qkv + base);
    __half2* k = (__half2*)(qkv + base + D_);
    float2 qf = __half22float2(*q);
    *q = __floats2half2_rn(qf.x * cs - qf.y * sn, qf.y * cs + qf.x * sn);
    float2 kf = __half22float2(*k);
    *k = __floats2half2_rn(kf.x * cs - kf.y * sn, kf.y * cs + kf.x * sn);
}

// ---------------- fp16 flash attention: q-split QK, d-split PV ---------------
// 128 thr (4 warps). Warp w: QK+softmax for q rows [16w,16w+16);
// PV accumulates ALL 64 q over d-slice [64w, 64w+64).
// SMEM: Q 32KB @0 | K 2x16KB @32768 | V 2x16KB @65536 | P 2x4KB @98304
//       | r 2x256B @106496 | l 256B @107008
#define ATT_SMEM 107520
__global__ __launch_bounds__(128, 2) void attn_mma(const __half* __restrict__ qkv,
                                                   __half* __restrict__ ctx) {
    extern __shared__ char smraw[];
    const uint32_t sb = smem_u32(smraw);
    const int tid = threadIdx.x, w = tid >> 5, L = tid & 31;
    const int qb = gridDim.x - 1 - blockIdx.x;
    const int b = blockIdx.y >> 4, h = blockIdx.y & 15;
    const int qg0 = qb * 64;
    const __half* base = qkv + (size_t)b * S_ * NQKV;
    const int nkt = 2 * qb + 2;

    // ---- prologue: stage Q + K(0) ----
#pragma unroll
    for (int i = 0; i < 16; i++) {
        int f = tid + i * 128, q = f >> 5, dc = f & 31;
        int row = q * 4 + (dc >> 3);
        CPA16(sb + row * 128 + (((dc & 7) * 16) ^ ((q & 7) << 4)),
              base + (size_t)(qg0 + q) * NQKV + h * 256 + dc * 8);
    }
#pragma unroll
    for (int i = 0; i < 8; i++) {
        int f = tid + i * 128, key = f >> 5, dc = f & 31;
        int row = key * 4 + (dc >> 3);
        CPA16(sb + 32768 + row * 128 + (((dc & 7) * 16) ^ ((key & 7) << 4)),
              base + (size_t)key * NQKV + D_ + h * 256 + dc * 8);
    }
    asm volatile("cp.async.commit_group;" ::: "memory");

    // O: acc[mt][np][4] — all 64 q (mt), warp's 64 d (np*16 + fragment cols)
    float acc[4][8][4];
#pragma unroll
    for (int mt = 0; mt < 4; mt++)
#pragma unroll
        for (int nt = 0; nt < 8; nt++)
#pragma unroll
            for (int j = 0; j < 4; j++) acc[mt][nt][j] = 0.f;
    float mlo = -1e30f, mhi = -1e30f, llo = 0.f, lhi = 0.f;

    // rescale O by per-row factors, then O += P(Pb) @ V(Vb)  (d-split)
    auto pv_step = [&](uint32_t Pb, uint32_t Vb, const float* rArr) {
#pragma unroll
        for (int mt = 0; mt < 4; mt++) {
            float r0 = rArr[16 * mt + (L >> 2)];
            float r1 = rArr[16 * mt + 8 + (L >> 2)];
#pragma unroll
            for (int nt = 0; nt < 8; nt++) {
                acc[mt][nt][0] *= r0; acc[mt][nt][1] *= r0;
                acc[mt][nt][2] *= r1; acc[mt][nt][3] *= r1;
            }
        }
#pragma unroll
        for (int ks2 = 0; ks2 < 2; ks2++) {
            uint32_t a[4][4];
#pragma unroll
            for (int mt = 0; mt < 4; mt++) {
                int q = 16 * mt + (L & 15);
                ldsm4(a[mt][0], a[mt][1], a[mt][2], a[mt][3],
                      Pb + (q >> 1) * 128 + (q & 1) * 64 +
                      ((uint32_t)((2 * ks2 + (L >> 4)) * 16) ^ (((q >> 1) & 3) << 4)));
            }
#pragma unroll
            for (int np = 0; np < 4; np++) {
                int key = ks2 * 16 + (L & 15);
                int dchunk = (4 * w + np) * 2 + (L >> 4);
                uint32_t m0, m1, m2, m3;
                ldsm4t(m0, m1, m2, m3,
                       Vb + (key * 4 + (dchunk >> 3)) * 128 +
                       (((dchunk & 7) * 16) ^ ((key & 7) << 4)));
#pragma unroll
                for (int mt = 0; mt < 4; mt++) {
                    MMA16(acc[mt][2 * np], a[mt], m0, m1);
                    MMA16(acc[mt][2 * np + 1], a[mt], m2, m3);
                }
            }
        }
    };

#pragma unroll 1
    for (int kt = 0; kt < nkt; kt++) {
        const int k0 = kt * 32, buf = kt & 1;
        const uint32_t Kb = sb + 32768 + buf * 16384;

        asm volatile("cp.async.wait_group 0;" ::: "memory");
        __syncthreads();    // staging barrier; also publishes P(kt-1), r(kt-1)

        // commit next loads: K(kt+1) -> buf^1, V(kt) -> buf
        {
#pragma unroll
            for (int i = 0; i < 8; i++) {
                int f = tid + i * 128, key = f >> 5, dc = f & 31;
                int row = key * 4 + (dc >> 3);
                uint32_t off = row * 128 + (((dc & 7) * 16) ^ ((key & 7) << 4));
                if (kt + 1 < nkt)
                    CPA16(sb + 32768 + (buf ^ 1) * 16384 + off,
                          base + (size_t)(k0 + 32 + key) * NQKV + D_ + h * 256 + dc * 8);
                CPA16(sb + 65536 + buf * 16384 + off,
                      base + (size_t)(k0 + key) * NQKV + 2 * D_ + h * 256 + dc * 8);
            }
            asm volatile("cp.async.commit_group;" ::: "memory");
        }

        // ---- QK(kt) mma stream (q-split) ----
        float s[4][4];
#pragma unroll
        for (int nt = 0; nt < 4; nt++)
#pragma unroll
            for (int j = 0; j < 4; j++) s[nt][j] = 0.f;
#pragma unroll
        for (int ks = 0; ks < 16; ks++) {
            uint32_t a[4];
            int q = 16 * w + (L & 15);
            ldsm4(a[0], a[1], a[2], a[3],
                  sb + (q * 4 + (ks >> 2)) * 128 +
                  (((2 * (ks & 3) + (L >> 4)) * 16) ^ ((q & 7) << 4)));
#pragma unroll
            for (int np = 0; np < 2; np++) {
                int n = np * 16 + ((L & 7) | ((L & 16) >> 1));
                uint32_t b0, b1, b2, b3;
                ldsm4(b0, b1, b2, b3,
                      Kb + (n * 4 + (ks >> 2)) * 128 +
                      (((2 * (ks & 3) + ((L >> 3) & 1)) * 16) ^ ((n & 7) << 4)));
                MMA16(s[2 * np], a, b0, b1);
                MMA16(s[2 * np + 1], a, b2, b3);
            }
        }

        // ---- delayed d-split PV(kt-1) under QK's shadow ----
        if (kt > 0) {
            pv_step(sb + 98304 + ((kt - 1) & 1) * 4096,
                    sb + 65536 + ((kt - 1) & 1) * 16384,
                    (const float*)(smraw + 106496 + ((kt - 1) & 1) * 256));
        }

        // ---- softmax(kt), q-split ----
#pragma unroll
        for (int nt = 0; nt < 4; nt++)
#pragma unroll
            for (int j = 0; j < 4; j++) s[nt][j] *= 0.0625f;
        if (k0 + 31 > qg0 + 16 * w) {
            int glo = qg0 + 16 * w + (L >> 2);
#pragma unroll
            for (int nt = 0; nt < 4; nt++) {
                int col = k0 + nt * 8 + 2 * (L & 3);
                if (col > glo)         s[nt][0] = -1e30f;
                if (col + 1 > glo)     s[nt][1] = -1e30f;
                if (col > glo + 8)     s[nt][2] = -1e30f;
                if (col + 1 > glo + 8) s[nt][3] = -1e30f;
            }
        }
        float tlo = -1e30f, thi = -1e30f;
#pragma unroll
        for (int nt = 0; nt < 4; nt++) {
            tlo = fmaxf(tlo, fmaxf(s[nt][0], s[nt][1]));
            thi = fmaxf(thi, fmaxf(s[nt][2], s[nt][3]));
        }
        tlo = fmaxf(tlo, __shfl_xor_sync(0xffffffffu, tlo, 1));
        tlo = fmaxf(tlo, __shfl_xor_sync(0xffffffffu, tlo, 2));
        thi = fmaxf(thi, __shfl_xor_sync(0xffffffffu, thi, 1));
        thi = fmaxf(thi, __shfl_xor_sync(0xffffffffu, thi, 2));
        float mnl = fmaxf(mlo, tlo), mnh = fmaxf(mhi, thi);
        float rlo = __expf(mlo - mnl), rhi = __expf(mhi - mnh);
        mlo = mnl; mhi = mnh;
        // publish per-row rescale factors for this tile
        {
            float* rArr = (float*)(smraw + 106496 + (kt & 1) * 256);
            if ((L & 3) == 0) {
                rArr[16 * w + (L >> 2)] = rlo;
                rArr[16 * w + 8 + (L >> 2)] = rhi;
            }
        }
        float psl = 0.f, psh = 0.f;
        {
            int qlo = 16 * w + (L >> 2);
            int qhi = qlo + 8;
            uint32_t Pw = (uint32_t)(98304 + (kt & 1) * 4096);
#pragma unroll
            for (int nt = 0; nt < 4; nt++) {
                float p0 = __expf(s[nt][0] - mnl);
                float p1 = __expf(s[nt][1] - mnl);
                float p2 = __expf(s[nt][2] - mnh);
                float p3 = __expf(s[nt][3] - mnh);
                psl += p0 + p1; psh += p2 + p3;
                uint32_t cb = (uint32_t)(nt * 16 + 4 * (L & 3));
                *(__half2*)(smraw + Pw + (qlo >> 1) * 128 + (qlo & 1) * 64 +
                            (cb ^ (((qlo >> 1) & 3) << 4))) = __floats2half2_rn(p0, p1);
                *(__half2*)(smraw + Pw + (qhi >> 1) * 128 + (qhi & 1) * 64 +
                            (cb ^ (((qhi >> 1) & 3) << 4))) = __floats2half2_rn(p2, p3);
            }
        }
        psl += __shfl_xor_sync(0xffffffffu, psl, 1);
        psl += __shfl_xor_sync(0xffffffffu, psl, 2);
        psh += __shfl_xor_sync(0xffffffffu, psh, 1);
        psh += __shfl_xor_sync(0xffffffffu, psh, 2);
        llo = llo * rlo + psl;
        lhi = lhi * rhi + psh;
    }

    // ---- epilogue: final PV, broadcast l, normalize, store ----
    asm volatile("cp.async.wait_group 0;" ::: "memory");
    __syncthreads();    // publishes P(nkt-1), r(nkt-1), V(nkt-1)
    pv_step(sb + 98304 + ((nkt - 1) & 1) * 4096,
            sb + 65536 + ((nkt - 1) & 1) * 16384,
            (const float*)(smraw + 106496 + ((nkt - 1) & 1) * 256));

    {
        float* lArr = (float*)(smraw + 107008);
        if ((L & 3) == 0) {
            lArr[16 * w + (L >> 2)] = llo;
            lArr[16 * w + 8 + (L >> 2)] = lhi;
        }
    }
    __syncthreads();
    const float* lArr = (const float*)(smraw + 107008);
#pragma unroll
    for (int mt = 0; mt < 4; mt++) {
        float il0 = 1.f / lArr[16 * mt + (L >> 2)];
        float il1 = 1.f / lArr[16 * mt + 8 + (L >> 2)];
        __half* cp = ctx + ((size_t)(b * S_ + qg0 + 16 * mt + (L >> 2))) * D_ +
                     h * 256 + 64 * w + 2 * (L & 3);
#pragma unroll
        for (int nt = 0; nt < 8; nt++) {
            *(__half2*)(cp + nt * 8) =
                __floats2half2_rn(acc[mt][nt][0] * il0, acc[mt][nt][1] * il0);
            *(__half2*)(cp + (size_t)8 * D_ + nt * 8) =
                __floats2half2_rn(acc[mt][nt][2] * il1, acc[mt][nt][3] * il1);
        }
    }
}

// ---------------- launch ------------------------------------------------------
extern "C" void kernel_launch(void* const* d_in, const int* in_sizes, int n_in,
                              void* d_out, int out_size) {
    const float* hs     = (const float*)d_in[0];
    const int*   qw_qkv = (const int*)  d_in[1];
    const int*   qz_qkv = (const int*)  d_in[2];
    const float* sc_qkv = (const float*)d_in[3];
    const int*   qw_out = (const int*)  d_in[4];
    const int*   qz_out = (const int*)  d_in[5];
    const float* sc_out = (const float*)d_in[6];
    float* out = (float*)d_out;

    __half *WqkvT, *qkv, *WoutT, *ctx, *hs16;
    cudaGetSymbolAddress((void**)&WqkvT, g_WqkvT);
    cudaGetSymbolAddress((void**)&qkv,   g_qkv);
    cudaGetSymbolAddress((void**)&WoutT, g_WoutT);
    cudaGetSymbolAddress((void**)&ctx,   g_ctx);
    cudaGetSymbolAddress((void**)&hs16,  g_hs16);

    cudaFuncSetAttribute(fp16_gemm,
                         cudaFuncAttributeMaxDynamicSharedMemorySize, 3 * STG4);
    cudaFuncSetAttribute(attn_mma,
                         cudaFuncAttributeMaxDynamicSharedMemorySize, ATT_SMEM);

    dequant_v2<<<(NQKV / 64) * 32, 256>>>(qw_qkv, qz_qkv, sc_qkv, WqkvT, NQKV);
    dequant_v2<<<(D_   / 64) * 32, 256>>>(qw_out, qz_out, sc_out, WoutT, D_);
    h16_copy_kernel<<<(MROWS * (D_ / 8)) / 256, 256>>>((const float4*)hs, (uint4*)hs16);

    fp16_gemm<<<(NQKV / 128) * (MROWS / 128), 128, 3 * STG4>>>(hs16, WqkvT, qkv, NQKV, 1);

    rope_kernel<<<B_ * S_, 512>>>(qkv);

    attn_mma<<<dim3(S_ / 64, 32), 128, ATT_SMEM>>>(qkv, ctx);

    fp16_gemm<<<(D_ / 128) * (MROWS / 128), 128, 3 * STG4>>>(ctx, WoutT, out, D_, 0);
}

// round 17
// speedup vs baseline: 1.0792x; 1.0792x over previous
#include <cuda_runtime.h>
#include <cuda_fp16.h>
#include <cstdint>

#define B_ 2
#define S_ 2048
#define D_ 4096
#define NQKV 12288
#define MROWS 4096

// ---------------- scratch (fp16 operands) ------------------------------------
__device__ __half g_WqkvT[(size_t)NQKV * D_];
__device__ __half g_qkv  [(size_t)MROWS * NQKV];
__device__ __half g_WoutT[(size_t)D_ * D_];
__device__ __half g_ctx  [(size_t)MROWS * D_];
__device__ __half g_hs16 [(size_t)MROWS * D_];

__device__ __forceinline__ uint32_t smem_u32(const void* p) {
    uint32_t a;
    asm("{ .reg .u64 t; cvta.to.shared.u64 t, %1; cvt.u32.u64 %0, t; }" : "=r"(a) : "l"(p));
    return a;
}
__device__ __forceinline__ void ldsm4(uint32_t& r0, uint32_t& r1, uint32_t& r2,
                                      uint32_t& r3, uint32_t addr) {
    asm volatile("ldmatrix.sync.aligned.m8n8.x4.shared.b16 {%0,%1,%2,%3}, [%4];"
                 : "=r"(r0), "=r"(r1), "=r"(r2), "=r"(r3) : "r"(addr));
}
__device__ __forceinline__ void ldsm4t(uint32_t& r0, uint32_t& r1, uint32_t& r2,
                                       uint32_t& r3, uint32_t addr) {
    asm volatile("ldmatrix.sync.aligned.m8n8.x4.trans.shared.b16 {%0,%1,%2,%3}, [%4];"
                 : "=r"(r0), "=r"(r1), "=r"(r2), "=r"(r3) : "r"(addr));
}
#define CPA16(dst, src) \
    asm volatile("cp.async.cg.shared.global [%0], [%1], 16;" :: "r"(dst), "l"(src))
#define MMA16(d, a, b0_, b1_) \
    asm volatile("mma.sync.aligned.m16n8k16.row.col.f32.f16.f16.f32 " \
                 "{%0,%1,%2,%3}, {%4,%5,%6,%7}, {%8,%9}, {%0,%1,%2,%3};" \
                 : "+f"(d[0]), "+f"(d[1]), "+f"(d[2]), "+f"(d[3]) \
                 : "r"(a[0]), "r"(a[1]), "r"(a[2]), "r"(a[3]), "r"(b0_), "r"(b1_))

// ---------------- GPTQ dequant v2 (R14, verified) ----------------------------
__global__ __launch_bounds__(256) void dequant_v2(const int* __restrict__ qw,
                                                  const int* __restrict__ qz,
                                                  const float* __restrict__ sc,
                                                  __half* __restrict__ Wt, int N) {
    __shared__ uint4 t[64][17];
    const int tid = threadIdx.x;
    const int ntiles = N >> 6;
    const int n0 = (blockIdx.x % ntiles) << 6;
    const int r0 = (blockIdx.x / ntiles) << 4;
    const int g = r0 >> 4;

#pragma unroll
    for (int i = 0; i < 4; i++) {
        int f = tid + i * 256;
        int nl = f & 63, rl = f >> 6;
        int n = n0 + nl, r = r0 + rl;
        unsigned w = (unsigned)qw[(size_t)r * N + n];
        unsigned z = (unsigned)qz[(size_t)g * (N / 8) + (n >> 3)];
        int zp = (int)((z >> ((n & 7) * 4)) & 15u) + 1;
        float s = sc[(size_t)g * N + n];
        __half2 h[4];
#pragma unroll
        for (int j = 0; j < 4; j++) {
            float v0 = s * (float)((int)((w >> (j * 8)) & 15u) - zp);
            float v1 = s * (float)((int)((w >> (j * 8 + 4)) & 15u) - zp);
            h[j] = __floats2half2_rn(v0, v1);
        }
        t[nl][rl] = *(uint4*)h;
    }
    __syncthreads();
#pragma unroll
    for (int i = 0; i < 4; i++) {
        int f = tid + i * 256;
        int nl = f >> 4, seg = f & 15;
        *(uint4*)(Wt + (size_t)(n0 + nl) * D_ + (size_t)r0 * 8 + seg * 8) = t[nl][seg];
    }
}

__global__ void h16_copy_kernel(const float4* __restrict__ src, uint4* __restrict__ dst) {
    size_t i = (size_t)blockIdx.x * blockDim.x + threadIdx.x;
    float4 a = src[2 * i], b = src[2 * i + 1];
    __half2 h[4] = {__floats2half2_rn(a.x, a.y), __floats2half2_rn(a.z, a.w),
                    __floats2half2_rn(b.x, b.y), __floats2half2_rn(b.z, b.w)};
    dst[i] = *(uint4*)h;
}

// ---------------- fp16 mma GEMM v5: spread LDGSTS under mma ------------------
#define STG4 32768
__global__ __launch_bounds__(128, 2) void fp16_gemm(const __half* __restrict__ A,
                                                    const __half* __restrict__ Bt,
                                                    void* __restrict__ Cv, int N,
                                                    int out_half) {
    extern __shared__ char smraw[];
    const uint32_t sb = smem_u32(smraw);
    const int tid = threadIdx.x;
    const int L = tid & 31;
    const int wid = tid >> 5;
    const int wm = wid >> 1, wn = wid & 1;

    const int gx = N >> 7;
    int rpg = gx << 4;
    int grp = blockIdx.x / rpg;
    int rem = blockIdx.x - grp * rpg;
    int by = (grp << 4) + (rem & 15);
    int bx = rem >> 4;

    const __half* Ag = A + (size_t)(by * 128) * 4096;
    const __half* Bg = Bt + (size_t)(bx * 128) * 4096;

    auto stage_load = [&](int kc, int st) {
        uint32_t sA = sb + st * STG4;
        uint32_t sB = sA + 16384;
        const __half* Ap = Ag + kc * 64;
        const __half* Bp = Bg + kc * 64;
#pragma unroll
        for (int i = 0; i < 8; i++) {
            int f = tid + i * 128, r = f >> 3, c = f & 7;
            uint32_t off = r * 128 + ((c * 16) ^ ((r & 7) << 4));
            CPA16(sA + off, Ap + (size_t)r * 4096 + c * 8);
            CPA16(sB + off, Bp + (size_t)r * 4096 + c * 8);
        }
        asm volatile("cp.async.commit_group;" ::: "memory");
    };

    float acc[4][8][4];
#pragma unroll
    for (int mt = 0; mt < 4; mt++)
#pragma unroll
        for (int nt = 0; nt < 8; nt++)
#pragma unroll
            for (int j = 0; j < 4; j++) acc[mt][nt][j] = 0.f;

    stage_load(0, 0);
    stage_load(1, 1);

#pragma unroll 1
    for (int i = 0; i < 64; i++) {
        if (i < 63) asm volatile("cp.async.wait_group 1;" ::: "memory");
        else        asm volatile("cp.async.wait_group 0;" ::: "memory");
        __syncthreads();
        uint32_t sA = sb + (i % 3) * STG4;
        uint32_t sB = sA + 16384;
        const bool pf = (i + 2 < 64);
        uint32_t dA = sb + ((i + 2) % 3) * STG4;
        uint32_t dB = dA + 16384;
        const __half* Ap = Ag + (i + 2) * 64;
        const __half* Bp = Bg + (i + 2) * 64;
#pragma unroll
        for (int ks = 0; ks < 4; ks++) {
            uint32_t a[4][4];
#pragma unroll
            for (int mt = 0; mt < 4; mt++) {
                int row = wm * 64 + mt * 16 + (L & 15);
                ldsm4(a[mt][0], a[mt][1], a[mt][2], a[mt][3],
                      sA + row * 128 + (((2 * ks + (L >> 4)) * 16) ^ ((row & 7) << 4)));
            }
#pragma unroll
            for (int np = 0; np < 4; np++) {
                int n = wn * 64 + np * 16 + ((L & 7) | ((L & 16) >> 1));
                uint32_t b0, b1, b2, b3;
                ldsm4(b0, b1, b2, b3,
                      sB + n * 128 + (((2 * ks + ((L >> 3) & 1)) * 16) ^ ((n & 7) << 4)));
#pragma unroll
                for (int mt = 0; mt < 4; mt++) {
                    MMA16(acc[mt][2 * np], a[mt], b0, b1);
                    MMA16(acc[mt][2 * np + 1], a[mt], b2, b3);
                }
            }
            // spread prefetch: 4 of 16 CPA16 per ks, issued under this ks's mma
            if (pf) {
#pragma unroll
                for (int j = 0; j < 2; j++) {
                    int f = tid + (ks * 2 + j) * 128, r = f >> 3, c = f & 7;
                    uint32_t off = r * 128 + ((c * 16) ^ ((r & 7) << 4));
                    CPA16(dA + off, Ap + (size_t)r * 4096 + c * 8);
                    CPA16(dB + off, Bp + (size_t)r * 4096 + c * 8);
                }
            }
        }
        if (pf) asm volatile("cp.async.commit_group;" ::: "memory");
    }

    const int row0 = by * 128 + wm * 64 + (L >> 2);
    const int col0 = bx * 128 + wn * 64 + 2 * (L & 3);
    if (out_half) {
        __half* C = (__half*)Cv;
#pragma unroll
        for (int mt = 0; mt < 4; mt++)
#pragma unroll
            for (int nt = 0; nt < 8; nt++) {
                __half* p = C + (size_t)(row0 + mt * 16) * N + col0 + nt * 8;
                *(__half2*)p = __floats2half2_rn(acc[mt][nt][0], acc[mt][nt][1]);
                *(__half2*)(p + (size_t)8 * N) = __floats2half2_rn(acc[mt][nt][2], acc[mt][nt][3]);
            }
    } else {
        float* C = (float*)Cv;
#pragma unroll
        for (int mt = 0; mt < 4; mt++)
#pragma unroll
            for (int nt = 0; nt < 8; nt++) {
                float* p = C + (size_t)(row0 + mt * 16) * N + col0 + nt * 8;
                *(float2*)p = make_float2(acc[mt][nt][0], acc[mt][nt][1]);
                *(float2*)(p + (size_t)8 * N) = make_float2(acc[mt][nt][2], acc[mt][nt][3]);
            }
    }
}

// ---------------- RoPE on fp16 qkv --------------------------------------------
__global__ void rope_kernel(__half* __restrict__ qkv) {
    int bs = blockIdx.x;
    int s = bs & (S_ - 1);
    int h = threadIdx.x >> 5;
    int i = threadIdx.x & 31;
    float inv_freq = 1.0f / powf(10000.0f, (float)(2 * i) / 64.0f);
    float ang = (float)s * inv_freq;
    float sn = sinf(ang), cs = cosf(ang);
    size_t base = (size_t)bs * NQKV + (size_t)h * 256 + 2 * i;
    __half2* q = (__half2*)(qkv + base);
    __half2* k = (__half2*)(qkv + base + D_);
    float2 qf = __half22float2(*q);
    *q = __floats2half2_rn(qf.x * cs - qf.y * sn, qf.y * cs + qf.x * sn);
    float2 kf = __half22float2(*k);
    *k = __floats2half2_rn(kf.x * cs - kf.y * sn, kf.y * cs + kf.x * sn);
}

// ---------------- fp16 flash attention (R14 measured-best, verbatim) ---------
#define ATT_SMEM 102400
__global__ __launch_bounds__(128, 2) void attn_mma(const __half* __restrict__ qkv,
                                                   __half* __restrict__ ctx) {
    extern __shared__ char smraw[];
    const uint32_t sb = smem_u32(smraw);
    const int tid = threadIdx.x, w = tid >> 5, L = tid & 31;
    const int qb = gridDim.x - 1 - blockIdx.x;
    const int b = blockIdx.y >> 4, h = blockIdx.y & 15;
    const int qg0 = qb * 64;
    const __half* base = qkv + (size_t)b * S_ * NQKV;
    const int nkt = 2 * qb + 2;

#pragma unroll
    for (int i = 0; i < 16; i++) {
        int f = tid + i * 128, q = f >> 5, dc = f & 31;
        int row = q * 4 + (dc >> 3);
        CPA16(sb + row * 128 + (((dc & 7) * 16) ^ ((q & 7) << 4)),
              base + (size_t)(qg0 + q) * NQKV + h * 256 + dc * 8);
    }
#pragma unroll
    for (int i = 0; i < 8; i++) {
        int f = tid + i * 128, key = f >> 5, dc = f & 31;
        int row = key * 4 + (dc >> 3);
        CPA16(sb + 32768 + row * 128 + (((dc & 7) * 16) ^ ((key & 7) << 4)),
              base + (size_t)key * NQKV + D_ + h * 256 + dc * 8);
    }
    asm volatile("cp.async.commit_group;" ::: "memory");

    float O[32][4];
#pragma unroll
    for (int nt = 0; nt < 32; nt++)
#pragma unroll
        for (int j = 0; j < 4; j++) O[nt][j] = 0.f;
    float mlo = -1e30f, mhi = -1e30f, llo = 0.f, lhi = 0.f;
    float rlo = 1.f, rhi = 1.f;

    auto pv_step = [&](uint32_t Vb) {
#pragma unroll
        for (int ks2 = 0; ks2 < 2; ks2++) {
            uint32_t a[4];
            int q = 16 * w + (L & 15);
            ldsm4(a[0], a[1], a[2], a[3],
                  sb + 98304 + (q >> 1) * 128 + (q & 1) * 64 +
                  ((uint32_t)((2 * ks2 + (L >> 4)) * 16) ^ (((q >> 1) & 3) << 4)));
#pragma unroll
            for (int np = 0; np < 16; np++) {
                int key = ks2 * 16 + (L & 15);
                int dchunk = np * 2 + (L >> 4);
                uint32_t m0, m1, m2, m3;
                ldsm4t(m0, m1, m2, m3,
                       Vb + (key * 4 + (dchunk >> 3)) * 128 +
                       (((dchunk & 7) * 16) ^ ((key & 7) << 4)));
                MMA16(O[2 * np], a, m0, m1);
                MMA16(O[2 * np + 1], a, m2, m3);
            }
        }
    };

#pragma unroll 1
    for (int kt = 0; kt < nkt; kt++) {
        const int k0 = kt * 32, buf = kt & 1;
        const uint32_t Kb = sb + 32768 + buf * 16384;

        asm volatile("cp.async.wait_group 0;" ::: "memory");
        __syncthreads();

        {
#pragma unroll
            for (int i = 0; i < 8; i++) {
                int f = tid + i * 128, key = f >> 5, dc = f & 31;
                int row = key * 4 + (dc >> 3);
                uint32_t off = row * 128 + (((dc & 7) * 16) ^ ((key & 7) << 4));
                if (kt + 1 < nkt)
                    CPA16(sb + 32768 + (buf ^ 1) * 16384 + off,
                          base + (size_t)(k0 + 32 + key) * NQKV + D_ + h * 256 + dc * 8);
                CPA16(sb + 65536 + buf * 16384 + off,
                      base + (size_t)(k0 + key) * NQKV + 2 * D_ + h * 256 + dc * 8);
            }
            asm volatile("cp.async.commit_group;" ::: "memory");
        }

        float s[4][4];
#pragma unroll
        for (int nt = 0; nt < 4; nt++)
#pragma unroll
            for (int j = 0; j < 4; j++) s[nt][j] = 0.f;
#pragma unroll
        for (int ks = 0; ks < 16; ks++) {
            uint32_t a[4];
            int q = 16 * w + (L & 15);
            ldsm4(a[0], a[1], a[2], a[3],
                  sb + (q * 4 + (ks >> 2)) * 128 +
                  (((2 * (ks & 3) + (L >> 4)) * 16) ^ ((q & 7) << 4)));
#pragma unroll
            for (int np = 0; np < 2; np++) {
                int n = np * 16 + ((L & 7) | ((L & 16) >> 1));
                uint32_t b0, b1, b2, b3;
                ldsm4(b0, b1, b2, b3,
                      Kb + (n * 4 + (ks >> 2)) * 128 +
                      (((2 * (ks & 3) + ((L >> 3) & 1)) * 16) ^ ((n & 7) << 4)));
                MMA16(s[2 * np], a, b0, b1);
                MMA16(s[2 * np + 1], a, b2, b3);
            }
        }

        if (kt > 0) {
#pragma unroll
            for (int nt = 0; nt < 32; nt++) {
                O[nt][0] *= rlo; O[nt][1] *= rlo; O[nt][2] *= rhi; O[nt][3] *= rhi;
            }
            pv_step(sb + 65536 + (buf ^ 1) * 16384);
        }
        __syncwarp();

#pragma unroll
        for (int nt = 0; nt < 4; nt++)
#pragma unroll
            for (int j = 0; j < 4; j++) s[nt][j] *= 0.0625f;
        if (k0 + 31 > qg0 + 16 * w) {
            int glo = qg0 + 16 * w + (L >> 2);
#pragma unroll
            for (int nt = 0; nt < 4; nt++) {
                int col = k0 + nt * 8 + 2 * (L & 3);
                if (col > glo)         s[nt][0] = -1e30f;
                if (col + 1 > glo)     s[nt][1] = -1e30f;
                if (col > glo + 8)     s[nt][2] = -1e30f;
                if (col + 1 > glo + 8) s[nt][3] = -1e30f;
            }
        }
        float tlo = -1e30f, thi = -1e30f;
#pragma unroll
        for (int nt = 0; nt < 4; nt++) {
            tlo = fmaxf(tlo, fmaxf(s[nt][0], s[nt][1]));
            thi = fmaxf(thi, fmaxf(s[nt][2], s[nt][3]));
        }
        tlo = fmaxf(tlo, __shfl_xor_sync(0xffffffffu, tlo, 1));
        tlo = fmaxf(tlo, __shfl_xor_sync(0xffffffffu, tlo, 2));
        thi = fmaxf(thi, __shfl_xor_sync(0xffffffffu, thi, 1));
        thi = fmaxf(thi, __shfl_xor_sync(0xffffffffu, thi, 2));
        float mnl = fmaxf(mlo, tlo), mnh = fmaxf(mhi, thi);
        rlo = __expf(mlo - mnl); rhi = __expf(mhi - mnh);
        mlo = mnl; mhi = mnh;
        float psl = 0.f, psh = 0.f;
        {
            int qlo = 16 * w + (L >> 2);
            int qhi = qlo + 8;
#pragma unroll
            for (int nt = 0; nt < 4; nt++) {
                float p0 = __expf(s[nt][0] - mnl);
                float p1 = __expf(s[nt][1] - mnl);
                float p2 = __expf(s[nt][2] - mnh);
                float p3 = __expf(s[nt][3] - mnh);
                psl += p0 + p1; psh += p2 + p3;
                uint32_t cb = (uint32_t)(nt * 16 + 4 * (L & 3));
                *(__half2*)(smraw + 98304 + (qlo >> 1) * 128 + (qlo & 1) * 64 +
                            (cb ^ (((qlo >> 1) & 3) << 4))) = __floats2half2_rn(p0, p1);
                *(__half2*)(smraw + 98304 + (qhi >> 1) * 128 + (qhi & 1) * 64 +
                            (cb ^ (((qhi >> 1) & 3) << 4))) = __floats2half2_rn(p2, p3);
            }
        }
        psl += __shfl_xor_sync(0xffffffffu, psl, 1);
        psl += __shfl_xor_sync(0xffffffffu, psl, 2);
        psh += __shfl_xor_sync(0xffffffffu, psh, 1);
        psh += __shfl_xor_sync(0xffffffffu, psh, 2);
        llo = llo * rlo + psl;
        lhi = lhi * rhi + psh;
        __syncwarp();
    }

    asm volatile("cp.async.wait_group 0;" ::: "memory");
    __syncthreads();
#pragma unroll
    for (int nt = 0; nt < 32; nt++) {
        O[nt][0] *= rlo; O[nt][1] *= rlo; O[nt][2] *= rhi; O[nt][3] *= rhi;
    }
    pv_step(sb + 65536 + ((nkt - 1) & 1) * 16384);

    float il = 1.f / llo, ih = 1.f / lhi;
    __half* cp = ctx + ((size_t)(b * S_ + qg0 + 16 * w + (L >> 2))) * D_ + h * 256 + 2 * (L & 3);
#pragma unroll
    for (int nt = 0; nt < 32; nt++) {
        *(__half2*)(cp + nt * 8) = __floats2half2_rn(O[nt][0] * il, O[nt][1] * il);
        *(__half2*)(cp + (size_t)8 * D_ + nt * 8) = __floats2half2_rn(O[nt][2] * ih, O[nt][3] * ih);
    }
}

// ---------------- launch ------------------------------------------------------
extern "C" void kernel_launch(void* const* d_in, const int* in_sizes, int n_in,
                              void* d_out, int out_size) {
    const float* hs     = (const float*)d_in[0];
    const int*   qw_qkv = (const int*)  d_in[1];
    const int*   qz_qkv = (const int*)  d_in[2];
    const float* sc_qkv = (const float*)d_in[3];
    const int*   qw_out = (const int*)  d_in[4];
    const int*   qz_out = (const int*)  d_in[5];
    const float* sc_out = (const float*)d_in[6];
    float* out = (float*)d_out;

    __half *WqkvT, *qkv, *WoutT, *ctx, *hs16;
    cudaGetSymbolAddress((void**)&WqkvT, g_WqkvT);
    cudaGetSymbolAddress((void**)&qkv,   g_qkv);
    cudaGetSymbolAddress((void**)&WoutT, g_WoutT);
    cudaGetSymbolAddress((void**)&ctx,   g_ctx);
    cudaGetSymbolAddress((void**)&hs16,  g_hs16);

    cudaFuncSetAttribute(fp16_gemm,
                         cudaFuncAttributeMaxDynamicSharedMemorySize, 3 * STG4);
    cudaFuncSetAttribute(attn_mma,
                         cudaFuncAttributeMaxDynamicSharedMemorySize, ATT_SMEM);

    dequant_v2<<<(NQKV / 64) * 32, 256>>>(qw_qkv, qz_qkv, sc_qkv, WqkvT, NQKV);
    dequant_v2<<<(D_   / 64) * 32, 256>>>(qw_out, qz_out, sc_out, WoutT, D_);
    h16_copy_kernel<<<(MROWS * (D_ / 8)) / 256, 256>>>((const float4*)hs, (uint4*)hs16);

    fp16_gemm<<<(NQKV / 128) * (MROWS / 128), 128, 3 * STG4>>>(hs16, WqkvT, qkv, NQKV, 1);

    rope_kernel<<<B_ * S_, 512>>>(qkv);

    attn_mma<<<dim3(S_ / 64, 32), 128, ATT_SMEM>>>(qkv, ctx);

    fp16_gemm<<<(D_ / 128) * (MROWS / 128), 128, 3 * STG4>>>(ctx, WoutT, out, D_, 0);
}